// round 16
// baseline (speedup 1.0000x reference)
#include <cuda_runtime.h>
#include <cstdint>

// ---------------- problem constants ----------------
#define NB   32        // batch
#define CIN  256
#define COUT 512
#define HW   16
#define KTOT 65536     // CIN*CIN
#define S3   128       // K-splits in main GEMM
#define KCH  32        // K per chunk
#define NCH  16        // W2 chunks per split
#define NBIAS 8        // extra bias chunks (K=256 from b2/Xsum)
#define OTB  256       // o rows per block
#define RS   36        // smem row stride in floats (conflict-free)

// compensate tf32 truncation of W2/b2 inside HMMA (mean relative shrink ~3.25e-4)
#define W2_TRUNC_COMP 1.000325f

#define CP_ASYNC16(dst, src) \
    asm volatile("cp.async.cg.shared.global [%0], [%1], 16;" :: "r"(dst), "l"(src))
#define CP_COMMIT() asm volatile("cp.async.commit_group;")
#define CP_WAIT(n)  asm volatile("cp.async.wait_group %0;" :: "n"(n))

// m16n8k8 tf32 HMMA (baseline sm_80+ feature)
#define MMA8(d0,d1,d2,d3, a0,a1,a2,a3, b0,b1) \
    asm volatile("mma.sync.aligned.m16n8k8.row.col.f32.tf32.tf32.f32 " \
        "{%0,%1,%2,%3}, {%4,%5,%6,%7}, {%8,%9}, {%0,%1,%2,%3};" \
        : "+f"(d0), "+f"(d1), "+f"(d2), "+f"(d3) \
        : "r"(a0), "r"(a1), "r"(a2), "r"(a3), "r"(b0), "r"(b1))

// ---------------- scratch ----------------
__device__ float g_y[NB * CIN * HW];                       // 512 KB
// chunks 0..2047: G; chunks 2048..2055: scaled/rounded Xsum (bias K-extension)
__device__ float g_G2[(KTOT / KCH + NBIAS) * NB * KCH];    // 8.4 MB

// ============================================================
// K1: y = relu(W1 x + b1) -> g_y; Xsum bias chunks -> g_G2; zero out
// grid (16, 32) = (c'-group of 16, b), 256 threads = 16 c' x 16 hw
// one output element per thread; unroll 8 -> 8 LDG.128 in flight
// ============================================================
__global__ void __launch_bounds__(256) k1_y(const float* __restrict__ x,
                                            const float* __restrict__ W1,
                                            const float* __restrict__ b1,
                                            float* __restrict__ out)
{
    __shared__ float xs[CIN * HW];   // 16 KB
    const int b  = blockIdx.y;
    const int cg = blockIdx.x;
    const int t  = threadIdx.x;

    // zero output: 512 blocks x 32 floats = 16384
    if (t < 32) out[(b * 16 + cg) * 32 + t] = 0.f;

    {
        const float4* xv  = (const float4*)(x + (size_t)b * CIN * HW);
        float4*       xsv = (float4*)xs;
        for (int i = t; i < CIN * HW / 4; i += 256) xsv[i] = xv[i];
    }
    __syncthreads();

    const int cpl = t >> 4;              // 0..15
    const int hw  = t & 15;
    const int cp  = cg * 16 + cpl;

    float acc = b1[cp];
    const float4* w1v = (const float4*)(W1 + (size_t)cp * CIN);
    #pragma unroll 8
    for (int c4 = 0; c4 < CIN / 4; c4++) {
        float4 w = w1v[c4];              // warp-broadcast (2 addrs/warp)
        const float* xp = xs + c4 * 4 * HW + hw;
        acc += w.x * xp[0] + w.y * xp[16] + w.z * xp[32] + w.w * xp[48];
    }
    g_y[((size_t)b * CIN + cp) * HW + hw] = fmaxf(acc, 0.f);

    if (cg == 0) {   // bias chunks: Xsum[b][c], c = t; scale + tf32-round
        float s = 0.f;
        #pragma unroll
        for (int h = 0; h < HW; h++) s += xs[t * HW + h];
        s *= W2_TRUNC_COMP;
        float vt;
        asm("cvt.rna.tf32.f32 %0, %1;" : "=f"(vt) : "f"(s));
        g_G2[(size_t)(KTOT / KCH + (t >> 5)) * (NB * KCH) + b * KCH + (t & 31)] = vt;
    }
}

// ============================================================
// K2: G[b][k] = sum_hw x[b,c,hw]*y[b,c',hw]; scale, round to tf32,
// write chunk-blocked g_G2[k>>5][b][k&31]
// grid (8, 32), 256 threads (thread = c')
// ============================================================
__global__ void __launch_bounds__(256) k2_G(const float* __restrict__ x)
{
    __shared__ float xs2[32 * HW];
    const int b  = blockIdx.y;
    const int cg = blockIdx.x;
    const int t  = threadIdx.x;

    {
        const float4* xv = (const float4*)(x + ((size_t)b * CIN + cg * 32) * HW);
        float4*       sv = (float4*)xs2;
        for (int i = t; i < 32 * HW / 4; i += 256) sv[i] = xv[i];
    }

    float yr[HW];
    {
        const float4* yv = (const float4*)(g_y + ((size_t)b * CIN + t) * HW);
        #pragma unroll
        for (int i = 0; i < 4; i++) {
            float4 v = yv[i];
            yr[i * 4 + 0] = v.x; yr[i * 4 + 1] = v.y; yr[i * 4 + 2] = v.z; yr[i * 4 + 3] = v.w;
        }
    }
    __syncthreads();

    const int wk  = t >> 5;
    const int kin = t & 31;

    #pragma unroll 4
    for (int j = 0; j < 32; j++) {
        const float* xj = xs2 + j * HW;
        float v = 0.f;
        #pragma unroll
        for (int h = 0; h < HW; h++) v += xj[h] * yr[h];
        v *= W2_TRUNC_COMP;
        float vt;
        asm("cvt.rna.tf32.f32 %0, %1;" : "=f"(vt) : "f"(v));
        int kc = (cg * 32 + j) * 8 + wk;
        g_G2[(size_t)kc * (NB * KCH) + b * KCH + kin] = vt;
    }
}

// ============================================================
// K3: tf32 HMMA GEMM + bias K-extension + red.global epilogue
// grid (COUT/OTB=2, S3=128), 256 threads (8 warps)  [proven 30.3us]
// ============================================================
#define SA_FBUF (OTB * RS)          // 9216 floats per A buffer
#define SB_FBUF (NB * RS)           // 1152 floats per B buffer
#define SMEM_K3 ((2 * SA_FBUF + 2 * SB_FBUF) * 4)   // 82944 bytes

__global__ void __launch_bounds__(256, 2) k3_gemm(const float* __restrict__ W2,
                                                  const float* __restrict__ b2,
                                                  float* __restrict__ out)
{
    extern __shared__ float dsm[];
    float* sA = dsm;                  // [2][OTB][RS]
    float* sB = dsm + 2 * SA_FBUF;    // [2][NB][RS]

    const int og   = blockIdx.x;
    const int s    = blockIdx.y;
    const int tid  = threadIdx.x;
    const int lane = tid & 31;
    const int w    = tid >> 5;
    const int g    = lane >> 2;
    const int t4   = lane & 3;
    const int o0B  = og * OTB;
    const int warpO = w * 32;
    const int kbase = s * (NCH * KCH);
    const int kc0   = kbase >> 5;

    const int cb   = s - (S3 - NBIAS);          // bias chunk id (valid when >= 0)
    const int nch  = (cb >= 0) ? NCH + 1 : NCH;

    const int sro = tid >> 3;   // 0..31
    const int skq = tid & 7;

    const unsigned sAaddr = (unsigned)__cvta_generic_to_shared(sA);
    const unsigned sBaddr = (unsigned)__cvta_generic_to_shared(sB);

    float d[2][4][4];
    #pragma unroll
    for (int mi = 0; mi < 2; mi++)
        #pragma unroll
        for (int ni = 0; ni < 4; ni++)
            #pragma unroll
            for (int r = 0; r < 4; r++) d[mi][ni][r] = 0.f;

    auto stage = [&](int ch, int buf) {
        if (ch < NCH) {
            const int k0 = kbase + ch * KCH;
            #pragma unroll
            for (int i = 0; i < 8; i++) {
                int row = sro + i * 32;
                const float* src = W2 + (size_t)(o0B + row) * KTOT + k0 + skq * 4;
                unsigned dst = sAaddr + (buf * SA_FBUF + row * RS + skq * 4) * 4;
                CP_ASYNC16(dst, src);
            }
            const float* src = g_G2 + (size_t)(kc0 + ch) * (NB * KCH) + sro * KCH + skq * 4;
            unsigned dst = sBaddr + (buf * SB_FBUF + sro * RS + skq * 4) * 4;
            CP_ASYNC16(dst, src);
        } else {
            // bias chunk: A rows from b2 (reshaped [COUT][CIN]), B = Xsum chunk
            #pragma unroll
            for (int i = 0; i < 8; i++) {
                int row = sro + i * 32;
                const float* src = b2 + (size_t)(o0B + row) * CIN + cb * KCH + skq * 4;
                unsigned dst = sAaddr + (buf * SA_FBUF + row * RS + skq * 4) * 4;
                CP_ASYNC16(dst, src);
            }
            const float* src = g_G2 + (size_t)(KTOT / KCH + cb) * (NB * KCH) + sro * KCH + skq * 4;
            unsigned dst = sBaddr + (buf * SB_FBUF + sro * RS + skq * 4) * 4;
            CP_ASYNC16(dst, src);
        }
    };

    stage(0, 0);
    CP_COMMIT();

    for (int ch = 0; ch < nch; ch++) {
        const int buf = ch & 1;
        if (ch + 1 < nch) {
            stage(ch + 1, buf ^ 1);
            CP_COMMIT();
            CP_WAIT(1);
        } else {
            CP_WAIT(0);
        }
        __syncthreads();

        const float* A = sA + buf * SA_FBUF;
        const float* B = sB + buf * SB_FBUF;

        #pragma unroll
        for (int k8 = 0; k8 < 4; k8++) {
            const int kq0 = k8 * 8;

            unsigned bf[4][2];
            #pragma unroll
            for (int ni = 0; ni < 4; ni++) {
                const float* bp = B + (ni * 8 + g) * RS + kq0 + t4;
                bf[ni][0] = __float_as_uint(bp[0]);
                bf[ni][1] = __float_as_uint(bp[4]);
            }
            unsigned af[2][4];
            #pragma unroll
            for (int mi = 0; mi < 2; mi++) {
                const float* ap = A + (warpO + mi * 16 + g) * RS + kq0 + t4;
                af[mi][0] = __float_as_uint(ap[0]);
                af[mi][1] = __float_as_uint(ap[8 * RS]);
                af[mi][2] = __float_as_uint(ap[4]);
                af[mi][3] = __float_as_uint(ap[8 * RS + 4]);
            }
            #pragma unroll
            for (int mi = 0; mi < 2; mi++)
                #pragma unroll
                for (int ni = 0; ni < 4; ni++)
                    MMA8(d[mi][ni][0], d[mi][ni][1], d[mi][ni][2], d[mi][ni][3],
                         af[mi][0], af[mi][1], af[mi][2], af[mi][3],
                         bf[ni][0], bf[ni][1]);
        }
        __syncthreads();
    }

    // ---- epilogue: frags -> sT[b][o_local] (stride 264) -> red.global.add ----
    float* sT = dsm;   // reuse: 32*264 floats = 33.8 KB
    #pragma unroll
    for (int mi = 0; mi < 2; mi++) {
        const int ob = warpO + mi * 16 + g;
        #pragma unroll
        for (int ni = 0; ni < 4; ni++) {
            const int bb = ni * 8 + 2 * t4;
            sT[(bb    ) * 264 + ob    ] = d[mi][ni][0];
            sT[(bb + 1) * 264 + ob    ] = d[mi][ni][1];
            sT[(bb    ) * 264 + ob + 8] = d[mi][ni][2];
            sT[(bb + 1) * 264 + ob + 8] = d[mi][ni][3];
        }
    }
    __syncthreads();

    for (int i = tid; i < 32 * OTB; i += 256) {
        const int bb = i >> 8;          // 0..31
        const int oo = i & 255;
        float v = sT[bb * 264 + oo];
        float* po = out + (size_t)bb * COUT + o0B + oo;   // coalesced across lanes
        asm volatile("red.global.add.f32 [%0], %1;" :: "l"(po), "f"(v) : "memory");
    }
}

// ============================================================
extern "C" void kernel_launch(void* const* d_in, const int* in_sizes, int n_in,
                              void* d_out, int out_size)
{
    const float* x  = (const float*)d_in[0];
    const float* W1 = (const float*)d_in[1];
    const float* b1 = (const float*)d_in[2];
    const float* W2 = (const float*)d_in[3];
    const float* b2 = (const float*)d_in[4];
    // d_in[5] (Wa), d_in[6] (ba): attention branch is dead code in the reference.
    float* out = (float*)d_out;

    cudaFuncSetAttribute(k3_gemm, cudaFuncAttributeMaxDynamicSharedMemorySize, SMEM_K3);

    k1_y   <<<dim3(16, NB), 256>>>(x, W1, b1, out);
    k2_G   <<<dim3(8, NB), 256>>>(x);
    k3_gemm<<<dim3(COUT / OTB, S3), 256, SMEM_K3>>>(W2, b2, out);
}

// round 17
// speedup vs baseline: 1.0457x; 1.0457x over previous
#include <cuda_runtime.h>
#include <cstdint>

// ---------------- problem constants ----------------
#define NB   32        // batch
#define CIN  256
#define COUT 512
#define HW   16
#define KTOT 65536     // CIN*CIN
#define S3   128       // K-splits in main GEMM
#define KCH  32        // K per chunk
#define NCH  16        // W2 chunks per split
#define NBIAS 8        // extra bias chunks (K=256 from b2/Xsum)
#define OTB  256       // o rows per block
#define RS   36        // smem row stride in floats (conflict-free)
#define XTS  260       // k1 transposed-x row stride (floats)

// compensate tf32 truncation of W2/b2 inside HMMA (mean relative shrink ~3.25e-4)
#define W2_TRUNC_COMP 1.000325f

#define CP_ASYNC16(dst, src) \
    asm volatile("cp.async.cg.shared.global [%0], [%1], 16;" :: "r"(dst), "l"(src))
#define CP_COMMIT() asm volatile("cp.async.commit_group;")
#define CP_WAIT(n)  asm volatile("cp.async.wait_group %0;" :: "n"(n))

// m16n8k8 tf32 HMMA (baseline sm_80+ feature)
#define MMA8(d0,d1,d2,d3, a0,a1,a2,a3, b0,b1) \
    asm volatile("mma.sync.aligned.m16n8k8.row.col.f32.tf32.tf32.f32 " \
        "{%0,%1,%2,%3}, {%4,%5,%6,%7}, {%8,%9}, {%0,%1,%2,%3};" \
        : "+f"(d0), "+f"(d1), "+f"(d2), "+f"(d3) \
        : "r"(a0), "r"(a1), "r"(a2), "r"(a3), "r"(b0), "r"(b1))

// ---------------- scratch ----------------
__device__ float g_y[NB * CIN * HW];                       // 512 KB
// chunks 0..2047: G; chunks 2048..2055: scaled/rounded Xsum (bias K-extension)
__device__ float g_G2[(KTOT / KCH + NBIAS) * NB * KCH];    // 8.4 MB

// ============================================================
// K1: y = relu(W1 x + b1) -> g_y; Xsum bias chunks -> g_G2; zero out
// grid (16, 32) = (c'-group of 16, b), 256 threads = 16 c' x 16 hw
// x transposed in smem -> inner loop is LDS.128 + broadcast LDG.128 + 4 FMA
// 4 independent accumulators (short dependency chain)
// ============================================================
__global__ void __launch_bounds__(256) k1_y(const float* __restrict__ x,
                                            const float* __restrict__ W1,
                                            const float* __restrict__ b1,
                                            float* __restrict__ out)
{
    __shared__ float xt[HW * XTS];   // transposed x: [hw][c], ~16.6 KB
    const int b  = blockIdx.y;
    const int cg = blockIdx.x;
    const int t  = threadIdx.x;

    // zero output: 512 blocks x 32 floats = 16384
    if (t < 32) out[(b * 16 + cg) * 32 + t] = 0.f;

    // stage + transpose x[b]: read [c][hw] float4, scatter to [hw][c]
    {
        const float4* xv = (const float4*)(x + (size_t)b * CIN * HW);
        for (int i = t; i < CIN * HW / 4; i += 256) {
            float4 v = xv[i];
            const int c   = i >> 2;
            const int hw0 = (i & 3) * 4;
            xt[(hw0 + 0) * XTS + c] = v.x;
            xt[(hw0 + 1) * XTS + c] = v.y;
            xt[(hw0 + 2) * XTS + c] = v.z;
            xt[(hw0 + 3) * XTS + c] = v.w;
        }
    }
    __syncthreads();

    const int cpl = t >> 4;              // 0..15
    const int hw  = t & 15;
    const int cp  = cg * 16 + cpl;

    float a0 = b1[cp], a1 = 0.f, a2 = 0.f, a3 = 0.f;
    const float4* w1v = (const float4*)(W1 + (size_t)cp * CIN);
    const float*  xr  = xt + hw * XTS;
    #pragma unroll 8
    for (int c4 = 0; c4 < CIN / 4; c4++) {
        float4 w  = w1v[c4];                       // warp-broadcast (2 addrs/warp)
        float4 xv4 = *(const float4*)(xr + c4 * 4); // LDS.128, <=2-way conflict
        a0 += w.x * xv4.x;
        a1 += w.y * xv4.y;
        a2 += w.z * xv4.z;
        a3 += w.w * xv4.w;
    }
    g_y[((size_t)b * CIN + cp) * HW + hw] = fmaxf((a0 + a1) + (a2 + a3), 0.f);

    if (cg == 0) {   // bias chunks: Xsum[b][c], c = t; scale + tf32-round
        float s = 0.f;
        #pragma unroll
        for (int h = 0; h < HW; h++) s += xt[h * XTS + t];   // conflict-free
        s *= W2_TRUNC_COMP;
        float vt;
        asm("cvt.rna.tf32.f32 %0, %1;" : "=f"(vt) : "f"(s));
        g_G2[(size_t)(KTOT / KCH + (t >> 5)) * (NB * KCH) + b * KCH + (t & 31)] = vt;
    }
}

// ============================================================
// K2: G[b][k] = sum_hw x[b,c,hw]*y[b,c',hw]; scale, round to tf32,
// write chunk-blocked g_G2[k>>5][b][k&31]
// grid (8, 32), 256 threads (thread = c')
// ============================================================
__global__ void __launch_bounds__(256) k2_G(const float* __restrict__ x)
{
    __shared__ float xs2[32 * HW];
    const int b  = blockIdx.y;
    const int cg = blockIdx.x;
    const int t  = threadIdx.x;

    {
        const float4* xv = (const float4*)(x + ((size_t)b * CIN + cg * 32) * HW);
        float4*       sv = (float4*)xs2;
        for (int i = t; i < 32 * HW / 4; i += 256) sv[i] = xv[i];
    }

    float yr[HW];
    {
        const float4* yv = (const float4*)(g_y + ((size_t)b * CIN + t) * HW);
        #pragma unroll
        for (int i = 0; i < 4; i++) {
            float4 v = yv[i];
            yr[i * 4 + 0] = v.x; yr[i * 4 + 1] = v.y; yr[i * 4 + 2] = v.z; yr[i * 4 + 3] = v.w;
        }
    }
    __syncthreads();

    const int wk  = t >> 5;
    const int kin = t & 31;

    #pragma unroll 4
    for (int j = 0; j < 32; j++) {
        const float* xj = xs2 + j * HW;
        float v = 0.f;
        #pragma unroll
        for (int h = 0; h < HW; h++) v += xj[h] * yr[h];
        v *= W2_TRUNC_COMP;
        float vt;
        asm("cvt.rna.tf32.f32 %0, %1;" : "=f"(vt) : "f"(v));
        int kc = (cg * 32 + j) * 8 + wk;
        g_G2[(size_t)kc * (NB * KCH) + b * KCH + kin] = vt;
    }
}

// ============================================================
// K3: tf32 HMMA GEMM + bias K-extension + red.global epilogue
// grid (COUT/OTB=2, S3=128), 256 threads (8 warps)  [proven 30.3us]
// ============================================================
#define SA_FBUF (OTB * RS)          // 9216 floats per A buffer
#define SB_FBUF (NB * RS)           // 1152 floats per B buffer
#define SMEM_K3 ((2 * SA_FBUF + 2 * SB_FBUF) * 4)   // 82944 bytes

__global__ void __launch_bounds__(256, 2) k3_gemm(const float* __restrict__ W2,
                                                  const float* __restrict__ b2,
                                                  float* __restrict__ out)
{
    extern __shared__ float dsm[];
    float* sA = dsm;                  // [2][OTB][RS]
    float* sB = dsm + 2 * SA_FBUF;    // [2][NB][RS]

    const int og   = blockIdx.x;
    const int s    = blockIdx.y;
    const int tid  = threadIdx.x;
    const int lane = tid & 31;
    const int w    = tid >> 5;
    const int g    = lane >> 2;
    const int t4   = lane & 3;
    const int o0B  = og * OTB;
    const int warpO = w * 32;
    const int kbase = s * (NCH * KCH);
    const int kc0   = kbase >> 5;

    const int cb   = s - (S3 - NBIAS);          // bias chunk id (valid when >= 0)
    const int nch  = (cb >= 0) ? NCH + 1 : NCH;

    const int sro = tid >> 3;   // 0..31
    const int skq = tid & 7;

    const unsigned sAaddr = (unsigned)__cvta_generic_to_shared(sA);
    const unsigned sBaddr = (unsigned)__cvta_generic_to_shared(sB);

    float d[2][4][4];
    #pragma unroll
    for (int mi = 0; mi < 2; mi++)
        #pragma unroll
        for (int ni = 0; ni < 4; ni++)
            #pragma unroll
            for (int r = 0; r < 4; r++) d[mi][ni][r] = 0.f;

    auto stage = [&](int ch, int buf) {
        if (ch < NCH) {
            const int k0 = kbase + ch * KCH;
            #pragma unroll
            for (int i = 0; i < 8; i++) {
                int row = sro + i * 32;
                const float* src = W2 + (size_t)(o0B + row) * KTOT + k0 + skq * 4;
                unsigned dst = sAaddr + (buf * SA_FBUF + row * RS + skq * 4) * 4;
                CP_ASYNC16(dst, src);
            }
            const float* src = g_G2 + (size_t)(kc0 + ch) * (NB * KCH) + sro * KCH + skq * 4;
            unsigned dst = sBaddr + (buf * SB_FBUF + sro * RS + skq * 4) * 4;
            CP_ASYNC16(dst, src);
        } else {
            // bias chunk: A rows from b2 (reshaped [COUT][CIN]), B = Xsum chunk
            #pragma unroll
            for (int i = 0; i < 8; i++) {
                int row = sro + i * 32;
                const float* src = b2 + (size_t)(o0B + row) * CIN + cb * KCH + skq * 4;
                unsigned dst = sAaddr + (buf * SA_FBUF + row * RS + skq * 4) * 4;
                CP_ASYNC16(dst, src);
            }
            const float* src = g_G2 + (size_t)(KTOT / KCH + cb) * (NB * KCH) + sro * KCH + skq * 4;
            unsigned dst = sBaddr + (buf * SB_FBUF + sro * RS + skq * 4) * 4;
            CP_ASYNC16(dst, src);
        }
    };

    stage(0, 0);
    CP_COMMIT();

    for (int ch = 0; ch < nch; ch++) {
        const int buf = ch & 1;
        if (ch + 1 < nch) {
            stage(ch + 1, buf ^ 1);
            CP_COMMIT();
            CP_WAIT(1);
        } else {
            CP_WAIT(0);
        }
        __syncthreads();

        const float* A = sA + buf * SA_FBUF;
        const float* B = sB + buf * SB_FBUF;

        #pragma unroll
        for (int k8 = 0; k8 < 4; k8++) {
            const int kq0 = k8 * 8;

            unsigned bf[4][2];
            #pragma unroll
            for (int ni = 0; ni < 4; ni++) {
                const float* bp = B + (ni * 8 + g) * RS + kq0 + t4;
                bf[ni][0] = __float_as_uint(bp[0]);
                bf[ni][1] = __float_as_uint(bp[4]);
            }
            unsigned af[2][4];
            #pragma unroll
            for (int mi = 0; mi < 2; mi++) {
                const float* ap = A + (warpO + mi * 16 + g) * RS + kq0 + t4;
                af[mi][0] = __float_as_uint(ap[0]);
                af[mi][1] = __float_as_uint(ap[8 * RS]);
                af[mi][2] = __float_as_uint(ap[4]);
                af[mi][3] = __float_as_uint(ap[8 * RS + 4]);
            }
            #pragma unroll
            for (int mi = 0; mi < 2; mi++)
                #pragma unroll
                for (int ni = 0; ni < 4; ni++)
                    MMA8(d[mi][ni][0], d[mi][ni][1], d[mi][ni][2], d[mi][ni][3],
                         af[mi][0], af[mi][1], af[mi][2], af[mi][3],
                         bf[ni][0], bf[ni][1]);
        }
        __syncthreads();
    }

    // ---- epilogue: frags -> sT[b][o_local] (stride 264) -> red.global.add ----
    float* sT = dsm;   // reuse: 32*264 floats = 33.8 KB
    #pragma unroll
    for (int mi = 0; mi < 2; mi++) {
        const int ob = warpO + mi * 16 + g;
        #pragma unroll
        for (int ni = 0; ni < 4; ni++) {
            const int bb = ni * 8 + 2 * t4;
            sT[(bb    ) * 264 + ob    ] = d[mi][ni][0];
            sT[(bb + 1) * 264 + ob    ] = d[mi][ni][1];
            sT[(bb    ) * 264 + ob + 8] = d[mi][ni][2];
            sT[(bb + 1) * 264 + ob + 8] = d[mi][ni][3];
        }
    }
    __syncthreads();

    for (int i = tid; i < 32 * OTB; i += 256) {
        const int bb = i >> 8;          // 0..31
        const int oo = i & 255;
        float v = sT[bb * 264 + oo];
        float* po = out + (size_t)bb * COUT + o0B + oo;   // coalesced across lanes
        asm volatile("red.global.add.f32 [%0], %1;" :: "l"(po), "f"(v) : "memory");
    }
}

// ============================================================
extern "C" void kernel_launch(void* const* d_in, const int* in_sizes, int n_in,
                              void* d_out, int out_size)
{
    const float* x  = (const float*)d_in[0];
    const float* W1 = (const float*)d_in[1];
    const float* b1 = (const float*)d_in[2];
    const float* W2 = (const float*)d_in[3];
    const float* b2 = (const float*)d_in[4];
    // d_in[5] (Wa), d_in[6] (ba): attention branch is dead code in the reference.
    float* out = (float*)d_out;

    cudaFuncSetAttribute(k3_gemm, cudaFuncAttributeMaxDynamicSharedMemorySize, SMEM_K3);

    k1_y   <<<dim3(16, NB), 256>>>(x, W1, b1, out);
    k2_G   <<<dim3(8, NB), 256>>>(x);
    k3_gemm<<<dim3(COUT / OTB, S3), 256, SMEM_K3>>>(W2, b2, out);
}